// round 1
// baseline (speedup 1.0000x reference)
#include <cuda_runtime.h>
#include <math.h>

#define NNODES 100000
#define NEDGES 640000
#define DD 128

// Scratch (allocation-free rule: __device__ globals)
__device__ float g_conv[NNODES * DD];   // scaled conv = (nodes@W2+b2)*rsqrt(sdeg)
__device__ float g_agg[NNODES * DD];    // edge-aggregated sum
__device__ int   g_sdeg[NNODES];
__device__ int   g_rdeg[NNODES];
__device__ float g_gvec[DD];            // globals@W3 + b3
__device__ float g_an[DD];              // sum over nodes of h

// ---------------------------------------------------------------- zeroing
__global__ void k_zero() {
    int i = blockIdx.x * blockDim.x + threadIdx.x;   // 12500*256 = 3.2M threads
    const int NA4 = NNODES * DD / 4;                 // 3,200,000 float4
    if (i < NA4) ((float4*)g_agg)[i] = make_float4(0.f, 0.f, 0.f, 0.f);
    if (i < NNODES) { g_sdeg[i] = 0; g_rdeg[i] = 0; }
    if (i < DD) g_an[i] = 0.f;
}

// ---------------------------------------------------------------- degrees
__global__ void k_deg(const int* __restrict__ snd, const int* __restrict__ rcv) {
    int e = blockIdx.x * blockDim.x + threadIdx.x;
    if (e < NEDGES) {
        atomicAdd(&g_sdeg[snd[e]], 1);
        atomicAdd(&g_rdeg[rcv[e]], 1);
    }
}

// ---------------------------------------------------------------- GEMM
// gridDim.y==0: h1 = nodes@W1 + b1          -> d_out (h region)
// gridDim.y==1: conv = (nodes@W2+b2)*rs     -> g_conv
// Block: 256 threads, 64 rows x 128 cols tile. Thread = (lane: 4 cols, ty: 8 rows).
__global__ __launch_bounds__(256) void k_gemm(
    const float* __restrict__ A,
    const float* __restrict__ W1, const float* __restrict__ b1,
    const float* __restrict__ W2, const float* __restrict__ b2,
    float* __restrict__ out_h)
{
    __shared__ float As[64 * DD];
    const int which = blockIdx.y;
    const float* W    = which ? W2 : W1;
    const float* bias = which ? b2 : b1;
    const int rowBase = blockIdx.x * 64;
    const int tid = threadIdx.x;
    const int maxr = NNODES - rowBase;          // valid rows in this tile

    // Load A tile [64 x 128] as float4, zero-pad OOB rows.
    const float4* A4 = (const float4*)(A + (long)rowBase * DD);
    float4* As4 = (float4*)As;
    #pragma unroll
    for (int i = 0; i < 8; i++) {
        int idx = tid + i * 256;                // float4 index; row = idx>>5
        float4 v = make_float4(0.f, 0.f, 0.f, 0.f);
        if ((idx >> 5) < maxr) v = A4[idx];
        As4[idx] = v;
    }
    __syncthreads();

    const int lane = tid & 31;                  // cols lane*4 .. +3
    const int ty   = tid >> 5;                  // rows ty*8 .. +7
    float4 acc[8];
    #pragma unroll
    for (int i = 0; i < 8; i++) acc[i] = make_float4(0.f, 0.f, 0.f, 0.f);

    const float4* W4 = (const float4*)W;
    #pragma unroll 8
    for (int k = 0; k < DD; k++) {
        float4 w = W4[k * 32 + lane];           // coalesced, L1-resident (64KB)
        #pragma unroll
        for (int i = 0; i < 8; i++) {
            float a = As[(ty * 8 + i) * DD + k];  // warp-broadcast LDS
            acc[i].x = fmaf(a, w.x, acc[i].x);
            acc[i].y = fmaf(a, w.y, acc[i].y);
            acc[i].z = fmaf(a, w.z, acc[i].z);
            acc[i].w = fmaf(a, w.w, acc[i].w);
        }
    }

    float4 bv = ((const float4*)bias)[lane];
    #pragma unroll
    for (int i = 0; i < 8; i++) {
        int r = ty * 8 + i;
        if (r < maxr) {
            int gr = rowBase + r;
            float4 o = acc[i];
            o.x += bv.x; o.y += bv.y; o.z += bv.z; o.w += bv.w;
            if (which) {
                float rs = rsqrtf(fmaxf((float)g_sdeg[gr], 1.0f));
                o.x *= rs; o.y *= rs; o.z *= rs; o.w *= rs;
                ((float4*)g_conv)[(long)gr * 32 + lane] = o;
            } else {
                ((float4*)out_h)[(long)gr * 32 + lane] = o;
            }
        }
    }
}

// ---------------------------------------------------------------- gvec = globals@W3 + b3
__global__ void k_gvec(const float* __restrict__ g, const float* __restrict__ W3,
                       const float* __restrict__ b3) {
    __shared__ float gs[DD];
    int c = threadIdx.x;                         // 128 threads
    gs[c] = g[c];
    __syncthreads();
    float acc = b3[c];
    #pragma unroll 8
    for (int k = 0; k < DD; k++) acc = fmaf(gs[k], W3[k * DD + c], acc);
    g_gvec[c] = acc;
}

// ---------------------------------------------------------------- edge scatter-add
// One warp per edge; lane handles 4 columns; 16B vector reductions.
__global__ __launch_bounds__(256) void k_agg(const int* __restrict__ snd,
                                             const int* __restrict__ rcv) {
    int warp = (blockIdx.x * 256 + threadIdx.x) >> 5;
    int lane = threadIdx.x & 31;
    if (warp < NEDGES) {
        int s = __ldg(&snd[warp]);               // uniform within warp
        int r = __ldg(&rcv[warp]);
        float4 v = ((const float4*)g_conv)[(long)s * 32 + lane];
        float* addr = &g_agg[(long)r * DD + lane * 4];
        asm volatile("red.global.add.v4.f32 [%0], {%1,%2,%3,%4};"
                     :: "l"(addr), "f"(v.x), "f"(v.y), "f"(v.z), "f"(v.w)
                     : "memory");
    }
}

// ---------------------------------------------------------------- fused epilogue + column sums
__global__ __launch_bounds__(256) void k_final(const float* __restrict__ nodes,
                                               float* __restrict__ out) {
    __shared__ float4 sred[256];
    const int tid  = threadIdx.x;
    const int lane = tid & 31;
    const int ty   = tid >> 5;
    const int rowBase = blockIdx.x * 64;
    float4 gv = ((const float4*)g_gvec)[lane];
    float4 sum = make_float4(0.f, 0.f, 0.f, 0.f);

    #pragma unroll
    for (int i = 0; i < 8; i++) {
        int r = rowBase + ty * 8 + i;
        if (r < NNODES) {
            long off = (long)r * 32 + lane;
            float4 h  = ((float4*)out)[off];
            float4 a  = ((const float4*)g_agg)[off];
            float4 nd = ((const float4*)nodes)[off];
            float rs = rsqrtf(fmaxf((float)g_rdeg[r], 1.0f));
            float4 o;
            o.x = fmaxf(h.x + a.x * rs + gv.x, 0.f) + nd.x;
            o.y = fmaxf(h.y + a.y * rs + gv.y, 0.f) + nd.y;
            o.z = fmaxf(h.z + a.z * rs + gv.z, 0.f) + nd.z;
            o.w = fmaxf(h.w + a.w * rs + gv.w, 0.f) + nd.w;
            ((float4*)out)[off] = o;
            sum.x += o.x; sum.y += o.y; sum.z += o.z; sum.w += o.w;
        }
    }
    sred[tid] = sum;
    __syncthreads();
    if (ty == 0) {
        float4 s = sred[lane];
        #pragma unroll
        for (int j = 1; j < 8; j++) {
            float4 t = sred[j * 32 + lane];
            s.x += t.x; s.y += t.y; s.z += t.z; s.w += t.w;
        }
        float* addr = &g_an[lane * 4];
        asm volatile("red.global.add.v4.f32 [%0], {%1,%2,%3,%4};"
                     :: "l"(addr), "f"(s.x), "f"(s.y), "f"(s.z), "f"(s.w)
                     : "memory");
    }
}

// ---------------------------------------------------------------- global update
__global__ void k_global(const float* __restrict__ g, const float* __restrict__ Wg,
                         const float* __restrict__ bg, float* __restrict__ outg) {
    __shared__ float an_s[DD], g_s[DD];
    int c = threadIdx.x;                         // 128 threads
    an_s[c] = g_an[c];
    g_s[c]  = g[c];
    __syncthreads();
    float acc = bg[c];
    #pragma unroll 8
    for (int k = 0; k < DD; k++) acc = fmaf(an_s[k], Wg[k * DD + c], acc);
    #pragma unroll 8
    for (int k = 0; k < DD; k++) acc = fmaf(g_s[k], Wg[(DD + k) * DD + c], acc);
    outg[c] = g_s[c] + fmaxf(acc, 0.f);
}

// ---------------------------------------------------------------- launch
extern "C" void kernel_launch(void* const* d_in, const int* in_sizes, int n_in,
                              void* d_out, int out_size) {
    const float* nodes    = (const float*)d_in[0];
    const float* globals_ = (const float*)d_in[1];
    const int*   senders   = (const int*)d_in[2];
    const int*   receivers = (const int*)d_in[3];
    const float* W1w = (const float*)d_in[4];
    const float* W1b = (const float*)d_in[5];
    const float* W2w = (const float*)d_in[6];
    const float* W2b = (const float*)d_in[7];
    const float* W3w = (const float*)d_in[8];
    const float* W3b = (const float*)d_in[9];
    const float* Wgw = (const float*)d_in[10];
    const float* Wgb = (const float*)d_in[11];
    float* out = (float*)d_out;

    k_zero<<<12500, 256>>>();
    k_deg<<<(NEDGES + 255) / 256, 256>>>(senders, receivers);
    dim3 gg((NNODES + 63) / 64, 2);
    k_gemm<<<gg, 256>>>(nodes, W1w, W1b, W2w, W2b, out);
    k_gvec<<<1, DD>>>(globals_, W3w, W3b);
    k_agg<<<(NEDGES + 7) / 8, 256>>>(senders, receivers);
    k_final<<<(NNODES + 63) / 64, 256>>>(nodes, out);
    k_global<<<1, DD>>>(globals_, Wgw, Wgb, out + (long)NNODES * DD);
}